// round 11
// baseline (speedup 1.0000x reference)
#include <cuda_runtime.h>
#include <cuda_fp16.h>
#include <cstdint>

// Problem constants
#define BATCH 256
#define TT    256
#define DM    384
#define DKV   64
#define BT    (BATCH*TT)

// ---------------------------------------------------------------------------
// Scratch
// ---------------------------------------------------------------------------
__device__ float g_q[BT * DKV];                       // q stays fp32 (hi/lo source)
__device__ __align__(16) __half g_kh[BT * DKV];       // k in fp16
__device__ __align__(16) __half g_vh[BT * DKV];       // v in fp16
// W^T packed [192 n][384 k], fp16. n: 0-63=Wq, 64-127=Wk, 128-191=Wv
__device__ __align__(16) __half g_wh[192 * DM];

// ---------------------------------------------------------------------------
// PTX helpers (sm_80-era: mma.sync + ldmatrix + cp.async, valid at compute_103)
// ---------------------------------------------------------------------------
__device__ __forceinline__ uint32_t smem_u32(const void* p) {
    uint32_t a;
    asm("{ .reg .u64 t; cvta.to.shared.u64 t, %1; cvt.u32.u64 %0, t; }"
        : "=r"(a) : "l"(p));
    return a;
}
__device__ __forceinline__ void ldsm_x4(uint32_t addr, uint32_t* r) {
    asm volatile("ldmatrix.sync.aligned.m8n8.x4.shared.b16 {%0,%1,%2,%3}, [%4];"
                 : "=r"(r[0]), "=r"(r[1]), "=r"(r[2]), "=r"(r[3]) : "r"(addr));
}
__device__ __forceinline__ void ldsm_x4t(uint32_t addr, uint32_t* r) {
    asm volatile("ldmatrix.sync.aligned.m8n8.x4.trans.shared.b16 {%0,%1,%2,%3}, [%4];"
                 : "=r"(r[0]), "=r"(r[1]), "=r"(r[2]), "=r"(r[3]) : "r"(addr));
}
__device__ __forceinline__ void mma_fp16(float* c, const uint32_t* a,
                                         uint32_t b0, uint32_t b1) {
    asm volatile(
        "mma.sync.aligned.m16n8k16.row.col.f32.f16.f16.f32 "
        "{%0,%1,%2,%3}, {%4,%5,%6,%7}, {%8,%9}, {%0,%1,%2,%3};"
        : "+f"(c[0]), "+f"(c[1]), "+f"(c[2]), "+f"(c[3])
        : "r"(a[0]), "r"(a[1]), "r"(a[2]), "r"(a[3]), "r"(b0), "r"(b1));
}
__device__ __forceinline__ float ex2(float x) {
    float y;
    asm("ex2.approx.ftz.f32 %0, %1;" : "=f"(y) : "f"(x));
    return y;
}
__device__ __forceinline__ void split2h(float x, float y, uint32_t& h, uint32_t& l) {
    __half h0 = __float2half_rn(x), h1 = __float2half_rn(y);
    __half l0 = __float2half_rn(x - __half2float(h0));
    __half l1 = __float2half_rn(y - __half2float(h1));
    __half2 hp = __halves2half2(h0, h1);
    __half2 lp = __halves2half2(l0, l1);
    h = *(uint32_t*)&hp; l = *(uint32_t*)&lp;
}
__device__ __forceinline__ uint32_t pack2h(float x, float y) {
    __half2 hp = __halves2half2(__float2half_rn(x), __float2half_rn(y));
    return *(uint32_t*)&hp;
}
#define CP_ASYNC16(dst, src) \
    asm volatile("cp.async.cg.shared.global [%0], [%1], 16;" \
                 :: "r"(dst), "l"(src) : "memory")
#define CP_COMMIT() asm volatile("cp.async.commit_group;" ::: "memory")
#define CP_WAIT(n)  asm volatile("cp.async.wait_group %0;" :: "n"(n) : "memory")

// ---------------------------------------------------------------------------
// Kernel 0: W^T fp16 conversion, coalesced reads via smem transpose.
// ---------------------------------------------------------------------------
__global__ void wconv_kernel(const float* __restrict__ Wq,
                             const float* __restrict__ Wk,
                             const float* __restrict__ Wv) {
    __shared__ float t[32][65];
    const int mat = blockIdx.x / 12;          // 0..2
    const int k0  = (blockIdx.x % 12) * 32;
    const float* W = (mat == 0) ? Wq : (mat == 1) ? Wk : Wv;
    const int tid = threadIdx.x;

    {
        const int n  = tid & 63;
        const int kl = tid >> 6;
        #pragma unroll
        for (int i = 0; i < 8; i++) {
            const int k = kl + i * 4;
            t[k][n] = W[(size_t)(k0 + k) * DKV + n];
        }
    }
    __syncthreads();
    {
        const int kl = tid & 31;
        const int nl = tid >> 5;
        #pragma unroll
        for (int i = 0; i < 8; i++) {
            const int n = nl + i * 8;
            g_wh[(size_t)(mat * 64 + n) * DM + k0 + kl] = __float2half_rn(t[kl][n]);
        }
    }
}

// ---------------------------------------------------------------------------
// Kernel 1: fused QKV projection, mma.sync fp16 single-pass, OCC 2.
//   BM=128 x BN=192 per CTA, K loop 12 x 32 (B traffic same as occ-1 shape).
//   A + B double-buffered (51.2 KB/CTA); regs capped at 128 for 2 CTAs/SM.
//   X staged in two 2xfloat4 rounds to keep staging regs at 8.
// ---------------------------------------------------------------------------
#define BM   128
#define BN   192
#define BKS  32
#define NKS  (DM / BKS)
#define PAD  40

#define A_SZ (BM * PAD)          // 5120
#define B_SZ (BN * PAD)          // 7680
#define OFF_A(buf)  ((buf) * A_SZ)
#define OFF_B(buf)  (2 * A_SZ + (buf) * B_SZ)
#define SM_ELEMS    (2 * A_SZ + 2 * B_SZ)            // 25600 fp16 = 51.2 KB

__global__ void __launch_bounds__(256, 2) proj_mma_kernel(const float* __restrict__ X) {
    extern __shared__ __half sm[];
    const uint32_t sb = smem_u32(sm);

    const int tid    = threadIdx.x;
    const int lane   = tid & 31;
    const int wid    = tid >> 5;
    const int warp_m = wid & 3;          // 4 warps along M: 32 rows each
    const int warp_n = wid >> 2;         // 2 warps along N: 96 cols each
    const int row0   = blockIdx.x * BM;

    float acc[2][12][4];
    #pragma unroll
    for (int m = 0; m < 2; m++)
        #pragma unroll
        for (int n = 0; n < 12; n++)
            #pragma unroll
            for (int j = 0; j < 4; j++) acc[m][n][j] = 0.f;

    const int br  = tid >> 2;            // B rows, strided by 64
    const int bc8 = tid & 3;

    auto cp_b = [&](int ks, int buf) {
        const int k0 = ks * BKS;
        #pragma unroll
        for (int i = 0; i < 3; i++) {
            int r = br + i * 64;
            uint32_t dst = sb + (uint32_t)(OFF_B(buf) + r * PAD + bc8 * 8) * 2;
            CP_ASYNC16(dst, g_wh + r * DM + k0 + bc8 * 8);
        }
    };
    // X: load + convert + store in two rounds of 2 float4 (8 staging regs)
    auto do_x = [&](int ks, int buf) {
        const int k0 = ks * BKS;
        #pragma unroll
        for (int half = 0; half < 2; half++) {
            float4 xa[2];
            #pragma unroll
            for (int i = 0; i < 2; i++) {
                int f  = tid + (half * 2 + i) * 256;
                int r  = f >> 3;
                int c4 = f & 7;
                xa[i] = *(const float4*)(X + (size_t)(row0 + r) * DM + k0 + c4 * 4);
            }
            #pragma unroll
            for (int i = 0; i < 2; i++) {
                int f  = tid + (half * 2 + i) * 256;
                int r  = f >> 3;
                int c4 = f & 7;
                *(uint2*)(sm + OFF_A(buf) + r * PAD + c4 * 4) =
                    make_uint2(pack2h(xa[i].x, xa[i].y), pack2h(xa[i].z, xa[i].w));
            }
        }
    };

    // ---- prologue ----
    cp_b(0, 0); CP_COMMIT();
    do_x(0, 0);
    CP_WAIT(0);
    __syncthreads();

    for (int ks = 0; ks < NKS; ks++) {
        const int cur = ks & 1;
        if (ks + 1 < NKS) { cp_b(ks + 1, cur ^ 1); CP_COMMIT(); }

        const uint32_t a_base = sb + OFF_A(cur) * 2;
        const uint32_t b_base = sb + OFF_B(cur) * 2;

        #pragma unroll
        for (int kk = 0; kk < 2; kk++) {
            uint32_t ah[2][4];
            const int arow_l = (lane & 15);
            const int acol   = kk * 16 + ((lane >> 4) << 3);
            #pragma unroll
            for (int mt = 0; mt < 2; mt++) {
                const int arow = warp_m * 32 + mt * 16 + arow_l;
                ldsm_x4(a_base + (uint32_t)(arow * PAD + acol) * 2, ah[mt]);
            }
            const int brow_l = (lane & 7) + ((lane & 16) >> 1);
            const int bcol   = kk * 16 + (lane & 8);
            #pragma unroll
            for (int g = 0; g < 6; g++) {
                uint32_t bh[4];
                const int brow = warp_n * 96 + g * 16 + brow_l;
                ldsm_x4(b_base + (uint32_t)(brow * PAD + bcol) * 2, bh);
                #pragma unroll
                for (int mt = 0; mt < 2; mt++) {
                    #pragma unroll
                    for (int h = 0; h < 2; h++) {
                        mma_fp16(acc[mt][g * 2 + h], ah[mt],
                                 bh[h * 2], bh[h * 2 + 1]);
                    }
                }
            }
        }

        if (ks + 1 < NKS) {
            do_x(ks + 1, cur ^ 1);           // different buffer: safe pre-barrier
            CP_WAIT(0);
            __syncthreads();
        }
    }

    // ---- epilogue: q -> fp32, k/v -> fp16 ----
    const int gi = lane >> 2;
    const int ti = lane & 3;
    #pragma unroll
    for (int mt = 0; mt < 2; mt++) {
        const int row = row0 + warp_m * 32 + mt * 16 + gi;
        #pragma unroll
        for (int nt = 0; nt < 12; nt++) {
            const int col = warp_n * 96 + nt * 8 + ti * 2;
            if (col < 64) {
                float* d0 = g_q + (size_t)row * DKV + col;
                float* d1 = g_q + (size_t)(row + 8) * DKV + col;
                *(float2*)d0 = make_float2(acc[mt][nt][0], acc[mt][nt][1]);
                *(float2*)d1 = make_float2(acc[mt][nt][2], acc[mt][nt][3]);
            } else {
                __half* dstbase = (col < 128) ? g_kh : g_vh;
                *(uint32_t*)(dstbase + (size_t)row * DKV + (col & 63)) =
                    pack2h(acc[mt][nt][0], acc[mt][nt][1]);
                *(uint32_t*)(dstbase + (size_t)(row + 8) * DKV + (col & 63)) =
                    pack2h(acc[mt][nt][2], acc[mt][nt][3]);
            }
        }
    }
}

// ---------------------------------------------------------------------------
// Kernel 2: causal attention, mma.sync fp16, 32-key softmax rounds.
//   K,V fp16 gmem -> cp.async smem; Q hi/lo (2-pass QK); P single-pass PV.
// ---------------------------------------------------------------------------
#define APAD 72
#define KV_SZ (TT * APAD)       // 18432 elems per buffer

__global__ void __launch_bounds__(256, 1) attn_mma_kernel(float* __restrict__ out) {
    extern __shared__ __half smk[];
    __half* Kh = smk;
    __half* Vh = smk + KV_SZ;

    const int b    = blockIdx.x;
    const int tid  = threadIdx.x;
    const int lane = tid & 31;
    const int wid  = tid >> 5;

    const uint32_t sbKh = smem_u32(Kh);
    const uint32_t sbVh = smem_u32(Vh);

    // ---- prologue: K,V fp16 gmem -> smem via cp.async ----
    {
        const __half* Kg = g_kh + (size_t)b * TT * DKV;
        const __half* Vg = g_vh + (size_t)b * TT * DKV;
        #pragma unroll
        for (int i0 = 0; i0 < 8; i0++) {
            int i = tid + i0 * 256;
            int r = i >> 3, c = i & 7;
            uint32_t off = (uint32_t)(r * APAD + c * 8) * 2;
            CP_ASYNC16(sbKh + off, Kg + r * DKV + c * 8);
            CP_ASYNC16(sbVh + off, Vg + r * DKV + c * 8);
        }
        CP_COMMIT();
    }

    // ---- Q fragments (gmem -> regs, hi/lo), overlapped with cp.async ----
    const int qb = (wid < 4) ? wid : (11 - wid);
    const int Q0 = qb * 32;
    const int g  = lane >> 2;
    const int tg = lane & 3;
    const float SC = 0.125f * 1.44269504f;

    uint32_t qh[2][4][4], ql[2][4][4];
    {
        const float* Qb = g_q + ((size_t)b * TT + Q0) * DKV;
        #pragma unroll
        for (int mt = 0; mt < 2; mt++) {
            #pragma unroll
            for (int kk = 0; kk < 4; kk++) {
                const int r0 = mt * 16 + g;
                const int c0 = kk * 16 + tg * 2;
                float2 v00 = *(const float2*)(Qb + r0 * DKV + c0);
                float2 v01 = *(const float2*)(Qb + r0 * DKV + c0 + 8);
                float2 v10 = *(const float2*)(Qb + (r0 + 8) * DKV + c0);
                float2 v11 = *(const float2*)(Qb + (r0 + 8) * DKV + c0 + 8);
                split2h(v00.x * SC, v00.y * SC, qh[mt][kk][0], ql[mt][kk][0]);
                split2h(v10.x * SC, v10.y * SC, qh[mt][kk][1], ql[mt][kk][1]);
                split2h(v01.x * SC, v01.y * SC, qh[mt][kk][2], ql[mt][kk][2]);
                split2h(v11.x * SC, v11.y * SC, qh[mt][kk][3], ql[mt][kk][3]);
            }
        }
    }
    CP_WAIT(0);
    __syncthreads();

    float m[4] = {-1e30f, -1e30f, -1e30f, -1e30f};
    float lsum[4] = {0.f, 0.f, 0.f, 0.f};
    float O[2][8][4];
    #pragma unroll
    for (int mt = 0; mt < 2; mt++)
        #pragma unroll
        for (int n = 0; n < 8; n++)
            #pragma unroll
            for (int j = 0; j < 4; j++) O[mt][n][j] = 0.f;

    const int krow = (lane & 7) + ((lane & 16) >> 1);
    const int koff = (lane & 8);
    const int vkey = lane & 15;
    const int voff = (lane >> 4) << 3;

    const int nrounds = qb + 1;
    for (int kr = 0; kr < nrounds; kr++) {
        const int j0 = kr * 32;
        const bool msk = (kr == qb);

        float S[2][4][4];
        #pragma unroll
        for (int mt = 0; mt < 2; mt++)
            #pragma unroll
            for (int nt = 0; nt < 4; nt++)
                #pragma unroll
                for (int j = 0; j < 4; j++) S[mt][nt][j] = 0.f;

        const uint32_t kb0 = sbKh + (uint32_t)((j0 + krow) * APAD + koff) * 2;
        const uint32_t kb1 = sbKh + (uint32_t)((j0 + 16 + krow) * APAD + koff) * 2;
        #pragma unroll
        for (int kk = 0; kk < 4; kk++) {
            uint32_t b0[4], b1[4];
            ldsm_x4(kb0 + kk * 32, b0);
            ldsm_x4(kb1 + kk * 32, b1);
            #pragma unroll
            for (int mt = 0; mt < 2; mt++) {
                mma_fp16(S[mt][0], qh[mt][kk], b0[0], b0[1]);
                mma_fp16(S[mt][1], qh[mt][kk], b0[2], b0[3]);
                mma_fp16(S[mt][2], qh[mt][kk], b1[0], b1[1]);
                mma_fp16(S[mt][3], qh[mt][kk], b1[2], b1[3]);
                mma_fp16(S[mt][0], ql[mt][kk], b0[0], b0[1]);
                mma_fp16(S[mt][1], ql[mt][kk], b0[2], b0[3]);
                mma_fp16(S[mt][2], ql[mt][kk], b1[0], b1[1]);
                mma_fp16(S[mt][3], ql[mt][kk], b1[2], b1[3]);
            }
        }

        if (msk) {
            #pragma unroll
            for (int mt = 0; mt < 2; mt++)
                #pragma unroll
                for (int nt = 0; nt < 4; nt++)
                    #pragma unroll
                    for (int j = 0; j < 4; j++) {
                        const int row = Q0 + mt * 16 + g + ((j >> 1) << 3);
                        const int col = j0 + nt * 8 + tg * 2 + (j & 1);
                        if (col > row) S[mt][nt][j] = -1e30f;
                    }
        }

        uint32_t pa0[2][4], pa1[2][4];
        #pragma unroll
        for (int mt = 0; mt < 2; mt++) {
            #pragma unroll
            for (int h = 0; h < 2; h++) {
                const int rg = mt * 2 + h;
                float v0 = S[mt][0][h * 2], v1 = S[mt][0][h * 2 + 1];
                float v2 = S[mt][1][h * 2], v3 = S[mt][1][h * 2 + 1];
                float v4 = S[mt][2][h * 2], v5 = S[mt][2][h * 2 + 1];
                float v6 = S[mt][3][h * 2], v7 = S[mt][3][h * 2 + 1];
                float mx = fmaxf(fmaxf(fmaxf(v0, v1), fmaxf(v2, v3)),
                                 fmaxf(fmaxf(v4, v5), fmaxf(v6, v7)));
                mx = fmaxf(mx, __shfl_xor_sync(0xFFFFFFFFu, mx, 1));
                mx = fmaxf(mx, __shfl_xor_sync(0xFFFFFFFFu, mx, 2));
                const float mnew = fmaxf(m[rg], mx);
                const float sc   = ex2(m[rg] - mnew);
                m[rg] = mnew;
                const float p0 = ex2(v0 - mnew), p1 = ex2(v1 - mnew);
                const float p2 = ex2(v2 - mnew), p3 = ex2(v3 - mnew);
                const float p4 = ex2(v4 - mnew), p5 = ex2(v5 - mnew);
                const float p6 = ex2(v6 - mnew), p7 = ex2(v7 - mnew);
                lsum[rg] = lsum[rg] * sc +
                           ((p0 + p1) + (p2 + p3)) + ((p4 + p5) + (p6 + p7));
                #pragma unroll
                for (int n = 0; n < 8; n++) {
                    O[mt][n][h * 2]     *= sc;
                    O[mt][n][h * 2 + 1] *= sc;
                }
                pa0[mt][h]     = pack2h(p0, p1);
                pa0[mt][2 + h] = pack2h(p2, p3);
                pa1[mt][h]     = pack2h(p4, p5);
                pa1[mt][2 + h] = pack2h(p6, p7);
            }
        }

        const uint32_t vb0 = sbVh + (uint32_t)((j0 + vkey) * APAD + voff) * 2;
        const uint32_t vb1 = sbVh + (uint32_t)((j0 + 16 + vkey) * APAD + voff) * 2;
        #pragma unroll
        for (int nc = 0; nc < 4; nc++) {
            uint32_t v0[4], v1[4];
            ldsm_x4t(vb0 + nc * 32, v0);
            ldsm_x4t(vb1 + nc * 32, v1);
            #pragma unroll
            for (int mt = 0; mt < 2; mt++) {
                mma_fp16(O[mt][nc * 2],     pa0[mt], v0[0], v0[1]);
                mma_fp16(O[mt][nc * 2 + 1], pa0[mt], v0[2], v0[3]);
                mma_fp16(O[mt][nc * 2],     pa1[mt], v1[0], v1[1]);
                mma_fp16(O[mt][nc * 2 + 1], pa1[mt], v1[2], v1[3]);
            }
        }
    }

    // ---- epilogue: quad-reduce l, normalize, store ----
    float inv[4];
    #pragma unroll
    for (int rg = 0; rg < 4; rg++) {
        float ls = lsum[rg];
        ls += __shfl_xor_sync(0xFFFFFFFFu, ls, 1);
        ls += __shfl_xor_sync(0xFFFFFFFFu, ls, 2);
        inv[rg] = 1.f / ls;
    }
    float* ob = out + ((size_t)b * TT) * DKV;
    #pragma unroll
    for (int mt = 0; mt < 2; mt++) {
        #pragma unroll
        for (int h = 0; h < 2; h++) {
            const int row = Q0 + mt * 16 + g + h * 8;
            const float iv = inv[mt * 2 + h];
            #pragma unroll
            for (int n = 0; n < 8; n++) {
                *(float2*)(ob + (size_t)row * DKV + n * 8 + tg * 2) =
                    make_float2(O[mt][n][h * 2] * iv, O[mt][n][h * 2 + 1] * iv);
            }
        }
    }
}

// ---------------------------------------------------------------------------
// kernel_launch — graph-capturable, allocation-free
// ---------------------------------------------------------------------------
extern "C" void kernel_launch(void* const* d_in, const int* in_sizes, int n_in,
                              void* d_out, int out_size) {
    const float* x  = (const float*)d_in[0];
    const float* Wq = (const float*)d_in[1];
    const float* Wk = (const float*)d_in[2];
    const float* Wv = (const float*)d_in[3];
    float* out = (float*)d_out;
    (void)in_sizes; (void)n_in; (void)out_size;

    wconv_kernel<<<36, 256>>>(Wq, Wk, Wv);

    const int proj_smem = SM_ELEMS * (int)sizeof(__half);        // 51.2 KB
    cudaFuncSetAttribute(proj_mma_kernel,
                         cudaFuncAttributeMaxDynamicSharedMemorySize, proj_smem);
    proj_mma_kernel<<<BT / BM, 256, proj_smem>>>(x);

    const int attn_smem = 2 * KV_SZ * (int)sizeof(__half);       // 72 KB
    cudaFuncSetAttribute(attn_mma_kernel,
                         cudaFuncAttributeMaxDynamicSharedMemorySize, attn_smem);
    attn_mma_kernel<<<BATCH, 256, attn_smem>>>(out);
}

// round 12
// speedup vs baseline: 1.0233x; 1.0233x over previous
#include <cuda_runtime.h>
#include <cuda_fp16.h>
#include <cstdint>

// Problem constants
#define BATCH 256
#define TT    256
#define DM    384
#define DKV   64
#define BT    (BATCH*TT)

// ---------------------------------------------------------------------------
// Scratch
// ---------------------------------------------------------------------------
__device__ float g_q[BT * DKV];                       // q stays fp32 (hi/lo source)
__device__ __align__(16) __half g_kh[BT * DKV];       // k in fp16
__device__ __align__(16) __half g_vh[BT * DKV];       // v in fp16
// W^T packed [192 n][384 k], fp16. n: 0-63=Wq, 64-127=Wk, 128-191=Wv
__device__ __align__(16) __half g_wh[192 * DM];

// ---------------------------------------------------------------------------
// PTX helpers (sm_80-era: mma.sync + ldmatrix + cp.async, valid at compute_103)
// ---------------------------------------------------------------------------
__device__ __forceinline__ uint32_t smem_u32(const void* p) {
    uint32_t a;
    asm("{ .reg .u64 t; cvta.to.shared.u64 t, %1; cvt.u32.u64 %0, t; }"
        : "=r"(a) : "l"(p));
    return a;
}
__device__ __forceinline__ void ldsm_x4(uint32_t addr, uint32_t* r) {
    asm volatile("ldmatrix.sync.aligned.m8n8.x4.shared.b16 {%0,%1,%2,%3}, [%4];"
                 : "=r"(r[0]), "=r"(r[1]), "=r"(r[2]), "=r"(r[3]) : "r"(addr));
}
__device__ __forceinline__ void ldsm_x4t(uint32_t addr, uint32_t* r) {
    asm volatile("ldmatrix.sync.aligned.m8n8.x4.trans.shared.b16 {%0,%1,%2,%3}, [%4];"
                 : "=r"(r[0]), "=r"(r[1]), "=r"(r[2]), "=r"(r[3]) : "r"(addr));
}
__device__ __forceinline__ void mma_fp16(float* c, const uint32_t* a,
                                         uint32_t b0, uint32_t b1) {
    asm volatile(
        "mma.sync.aligned.m16n8k16.row.col.f32.f16.f16.f32 "
        "{%0,%1,%2,%3}, {%4,%5,%6,%7}, {%8,%9}, {%0,%1,%2,%3};"
        : "+f"(c[0]), "+f"(c[1]), "+f"(c[2]), "+f"(c[3])
        : "r"(a[0]), "r"(a[1]), "r"(a[2]), "r"(a[3]), "r"(b0), "r"(b1));
}
__device__ __forceinline__ float ex2(float x) {
    float y;
    asm("ex2.approx.ftz.f32 %0, %1;" : "=f"(y) : "f"(x));
    return y;
}
__device__ __forceinline__ void split2h(float x, float y, uint32_t& h, uint32_t& l) {
    __half h0 = __float2half_rn(x), h1 = __float2half_rn(y);
    __half l0 = __float2half_rn(x - __half2float(h0));
    __half l1 = __float2half_rn(y - __half2float(h1));
    __half2 hp = __halves2half2(h0, h1);
    __half2 lp = __halves2half2(l0, l1);
    h = *(uint32_t*)&hp; l = *(uint32_t*)&lp;
}
__device__ __forceinline__ uint32_t pack2h(float x, float y) {
    __half2 hp = __halves2half2(__float2half_rn(x), __float2half_rn(y));
    return *(uint32_t*)&hp;
}
#define CP_ASYNC16(dst, src) \
    asm volatile("cp.async.cg.shared.global [%0], [%1], 16;" \
                 :: "r"(dst), "l"(src) : "memory")
#define CP_COMMIT() asm volatile("cp.async.commit_group;" ::: "memory")
#define CP_WAIT(n)  asm volatile("cp.async.wait_group %0;" :: "n"(n) : "memory")

// ---------------------------------------------------------------------------
// Kernel 0: W^T fp16 conversion, coalesced reads via smem transpose.
// ---------------------------------------------------------------------------
__global__ void wconv_kernel(const float* __restrict__ Wq,
                             const float* __restrict__ Wk,
                             const float* __restrict__ Wv) {
    __shared__ float t[32][65];
    const int mat = blockIdx.x / 12;          // 0..2
    const int k0  = (blockIdx.x % 12) * 32;
    const float* W = (mat == 0) ? Wq : (mat == 1) ? Wk : Wv;
    const int tid = threadIdx.x;

    {
        const int n  = tid & 63;
        const int kl = tid >> 6;
        #pragma unroll
        for (int i = 0; i < 8; i++) {
            const int k = kl + i * 4;
            t[k][n] = W[(size_t)(k0 + k) * DKV + n];
        }
    }
    __syncthreads();
    {
        const int kl = tid & 31;
        const int nl = tid >> 5;
        #pragma unroll
        for (int i = 0; i < 8; i++) {
            const int n = nl + i * 8;
            g_wh[(size_t)(mat * 64 + n) * DM + k0 + kl] = __float2half_rn(t[kl][n]);
        }
    }
}

// ---------------------------------------------------------------------------
// Kernel 1: fused QKV projection, mma.sync fp16 single-pass.
//   BM=128 x BN=192 per CTA, 512 THREADS (16 warps, warp tile 32x48).
//   A: triple buffer (reg-staged LDG + convert + STS), one sync per stage.
//   B: cp.async triple buffer, prefetch depth 2. Occ 1, 16 warps/SM.
// ---------------------------------------------------------------------------
#define BM   128
#define BN   192
#define BKS  32
#define NKS  (DM / BKS)
#define PAD  40

#define A_SZ (BM * PAD)          // 5120
#define B_SZ (BN * PAD)          // 7680
#define OFF_A(buf)  ((buf) * A_SZ)
#define OFF_B(buf)  (3 * A_SZ + (buf) * B_SZ)
#define SM_ELEMS    (3 * A_SZ + 3 * B_SZ)            // 38400 fp16 = 76.8 KB

__global__ void __launch_bounds__(512, 1) proj_mma_kernel(const float* __restrict__ X) {
    extern __shared__ __half sm[];
    const uint32_t sb = smem_u32(sm);

    const int tid    = threadIdx.x;
    const int lane   = tid & 31;
    const int wid    = tid >> 5;           // 0..15
    const int warp_m = wid & 3;            // 4 warps along M: 32 rows each
    const int warp_n = wid >> 2;           // 4 warps along N: 48 cols each
    const int row0   = blockIdx.x * BM;

    float acc[2][6][4];
    #pragma unroll
    for (int m = 0; m < 2; m++)
        #pragma unroll
        for (int n = 0; n < 6; n++)
            #pragma unroll
            for (int j = 0; j < 4; j++) acc[m][n][j] = 0.f;

    float4 xa[2];

    auto cp_b = [&](int ks, int buf) {
        const int k0 = ks * BKS;
        {
            int c = tid;                   // chunks 0..511
            int r = c >> 2, c8 = c & 3;
            uint32_t dst = sb + (uint32_t)(OFF_B(buf) + r * PAD + c8 * 8) * 2;
            CP_ASYNC16(dst, g_wh + r * DM + k0 + c8 * 8);
        }
        if (tid < 256) {                   // chunks 512..767
            int c = 512 + tid;
            int r = c >> 2, c8 = c & 3;
            uint32_t dst = sb + (uint32_t)(OFF_B(buf) + r * PAD + c8 * 8) * 2;
            CP_ASYNC16(dst, g_wh + r * DM + k0 + c8 * 8);
        }
    };
    auto load_x = [&](int ks) {
        const int k0 = ks * BKS;
        #pragma unroll
        for (int i = 0; i < 2; i++) {
            int f  = tid + i * 512;        // 0..1023
            int r  = f >> 3;
            int c4 = f & 7;
            xa[i] = *(const float4*)(X + (size_t)(row0 + r) * DM + k0 + c4 * 4);
        }
    };
    auto store_x = [&](int buf) {
        #pragma unroll
        for (int i = 0; i < 2; i++) {
            int f  = tid + i * 512;
            int r  = f >> 3;
            int c4 = f & 7;
            float4 v = xa[i];
            *(uint2*)(sm + OFF_A(buf) + r * PAD + c4 * 4) =
                make_uint2(pack2h(v.x, v.y), pack2h(v.z, v.w));
        }
    };

    // ---- prologue ----
    cp_b(0, 0); CP_COMMIT();
    cp_b(1, 1); CP_COMMIT();
    load_x(0);
    store_x(0);
    CP_WAIT(1);                      // B(0) landed
    __syncthreads();

    for (int ks = 0; ks < NKS; ks++) {
        if (ks + 2 < NKS) { cp_b(ks + 2, (ks + 2) % 3); CP_COMMIT(); }
        if (ks + 1 < NKS) load_x(ks + 1);

        const uint32_t a_base = sb + OFF_A(ks % 3) * 2;
        const uint32_t b_base = sb + OFF_B(ks % 3) * 2;

        #pragma unroll
        for (int kk = 0; kk < 2; kk++) {
            uint32_t ah[2][4];
            const int arow_l = (lane & 15);
            const int acol   = kk * 16 + ((lane >> 4) << 3);
            #pragma unroll
            for (int mt = 0; mt < 2; mt++) {
                const int arow = warp_m * 32 + mt * 16 + arow_l;
                ldsm_x4(a_base + (uint32_t)(arow * PAD + acol) * 2, ah[mt]);
            }
            const int brow_l = (lane & 7) + ((lane & 16) >> 1);
            const int bcol   = kk * 16 + (lane & 8);
            #pragma unroll
            for (int g = 0; g < 3; g++) {
                uint32_t bh[4];
                const int brow = warp_n * 48 + g * 16 + brow_l;
                ldsm_x4(b_base + (uint32_t)(brow * PAD + bcol) * 2, bh);
                #pragma unroll
                for (int mt = 0; mt < 2; mt++) {
                    #pragma unroll
                    for (int h = 0; h < 2; h++) {
                        mma_fp16(acc[mt][g * 2 + h], ah[mt],
                                 bh[h * 2], bh[h * 2 + 1]);
                    }
                }
            }
        }

        if (ks + 1 < NKS) {
            store_x((ks + 1) % 3);           // triple buffer: safe pre-barrier
            if (ks + 2 < NKS) { CP_WAIT(1); }
            else              { CP_WAIT(0); }
            __syncthreads();                 // single barrier per stage
        }
    }

    // ---- epilogue: q -> fp32, k/v -> fp16 ----
    const int gi = lane >> 2;
    const int ti = lane & 3;
    #pragma unroll
    for (int mt = 0; mt < 2; mt++) {
        const int row = row0 + warp_m * 32 + mt * 16 + gi;
        #pragma unroll
        for (int nt = 0; nt < 6; nt++) {
            const int col = warp_n * 48 + nt * 8 + ti * 2;
            if (col < 64) {
                float* d0 = g_q + (size_t)row * DKV + col;
                float* d1 = g_q + (size_t)(row + 8) * DKV + col;
                *(float2*)d0 = make_float2(acc[mt][nt][0], acc[mt][nt][1]);
                *(float2*)d1 = make_float2(acc[mt][nt][2], acc[mt][nt][3]);
            } else {
                __half* dstbase = (col < 128) ? g_kh : g_vh;
                *(uint32_t*)(dstbase + (size_t)row * DKV + (col & 63)) =
                    pack2h(acc[mt][nt][0], acc[mt][nt][1]);
                *(uint32_t*)(dstbase + (size_t)(row + 8) * DKV + (col & 63)) =
                    pack2h(acc[mt][nt][2], acc[mt][nt][3]);
            }
        }
    }
}

// ---------------------------------------------------------------------------
// Kernel 2: causal attention, mma.sync fp16, 32-key softmax rounds.
//   (unchanged from R10 — the 82.4us configuration)
// ---------------------------------------------------------------------------
#define APAD 72
#define KV_SZ (TT * APAD)       // 18432 elems per buffer

__global__ void __launch_bounds__(256, 1) attn_mma_kernel(float* __restrict__ out) {
    extern __shared__ __half smk[];
    __half* Kh = smk;
    __half* Vh = smk + KV_SZ;

    const int b    = blockIdx.x;
    const int tid  = threadIdx.x;
    const int lane = tid & 31;
    const int wid  = tid >> 5;

    const uint32_t sbKh = smem_u32(Kh);
    const uint32_t sbVh = smem_u32(Vh);

    // ---- prologue: K,V fp16 gmem -> smem via cp.async ----
    {
        const __half* Kg = g_kh + (size_t)b * TT * DKV;
        const __half* Vg = g_vh + (size_t)b * TT * DKV;
        #pragma unroll
        for (int i0 = 0; i0 < 8; i0++) {
            int i = tid + i0 * 256;
            int r = i >> 3, c = i & 7;
            uint32_t off = (uint32_t)(r * APAD + c * 8) * 2;
            CP_ASYNC16(sbKh + off, Kg + r * DKV + c * 8);
            CP_ASYNC16(sbVh + off, Vg + r * DKV + c * 8);
        }
        CP_COMMIT();
    }

    // ---- Q fragments (gmem -> regs, hi/lo), overlapped with cp.async ----
    const int qb = (wid < 4) ? wid : (11 - wid);
    const int Q0 = qb * 32;
    const int g  = lane >> 2;
    const int tg = lane & 3;
    const float SC = 0.125f * 1.44269504f;

    uint32_t qh[2][4][4], ql[2][4][4];
    {
        const float* Qb = g_q + ((size_t)b * TT + Q0) * DKV;
        #pragma unroll
        for (int mt = 0; mt < 2; mt++) {
            #pragma unroll
            for (int kk = 0; kk < 4; kk++) {
                const int r0 = mt * 16 + g;
                const int c0 = kk * 16 + tg * 2;
                float2 v00 = *(const float2*)(Qb + r0 * DKV + c0);
                float2 v01 = *(const float2*)(Qb + r0 * DKV + c0 + 8);
                float2 v10 = *(const float2*)(Qb + (r0 + 8) * DKV + c0);
                float2 v11 = *(const float2*)(Qb + (r0 + 8) * DKV + c0 + 8);
                split2h(v00.x * SC, v00.y * SC, qh[mt][kk][0], ql[mt][kk][0]);
                split2h(v10.x * SC, v10.y * SC, qh[mt][kk][1], ql[mt][kk][1]);
                split2h(v01.x * SC, v01.y * SC, qh[mt][kk][2], ql[mt][kk][2]);
                split2h(v11.x * SC, v11.y * SC, qh[mt][kk][3], ql[mt][kk][3]);
            }
        }
    }
    CP_WAIT(0);
    __syncthreads();

    float m[4] = {-1e30f, -1e30f, -1e30f, -1e30f};
    float lsum[4] = {0.f, 0.f, 0.f, 0.f};
    float O[2][8][4];
    #pragma unroll
    for (int mt = 0; mt < 2; mt++)
        #pragma unroll
        for (int n = 0; n < 8; n++)
            #pragma unroll
            for (int j = 0; j < 4; j++) O[mt][n][j] = 0.f;

    const int krow = (lane & 7) + ((lane & 16) >> 1);
    const int koff = (lane & 8);
    const int vkey = lane & 15;
    const int voff = (lane >> 4) << 3;

    const int nrounds = qb + 1;
    for (int kr = 0; kr < nrounds; kr++) {
        const int j0 = kr * 32;
        const bool msk = (kr == qb);

        float S[2][4][4];
        #pragma unroll
        for (int mt = 0; mt < 2; mt++)
            #pragma unroll
            for (int nt = 0; nt < 4; nt++)
                #pragma unroll
                for (int j = 0; j < 4; j++) S[mt][nt][j] = 0.f;

        const uint32_t kb0 = sbKh + (uint32_t)((j0 + krow) * APAD + koff) * 2;
        const uint32_t kb1 = sbKh + (uint32_t)((j0 + 16 + krow) * APAD + koff) * 2;
        #pragma unroll
        for (int kk = 0; kk < 4; kk++) {
            uint32_t b0[4], b1[4];
            ldsm_x4(kb0 + kk * 32, b0);
            ldsm_x4(kb1 + kk * 32, b1);
            #pragma unroll
            for (int mt = 0; mt < 2; mt++) {
                mma_fp16(S[mt][0], qh[mt][kk], b0[0], b0[1]);
                mma_fp16(S[mt][1], qh[mt][kk], b0[2], b0[3]);
                mma_fp16(S[mt][2], qh[mt][kk], b1[0], b1[1]);
                mma_fp16(S[mt][3], qh[mt][kk], b1[2], b1[3]);
                mma_fp16(S[mt][0], ql[mt][kk], b0[0], b0[1]);
                mma_fp16(S[mt][1], ql[mt][kk], b0[2], b0[3]);
                mma_fp16(S[mt][2], ql[mt][kk], b1[0], b1[1]);
                mma_fp16(S[mt][3], ql[mt][kk], b1[2], b1[3]);
            }
        }

        if (msk) {
            #pragma unroll
            for (int mt = 0; mt < 2; mt++)
                #pragma unroll
                for (int nt = 0; nt < 4; nt++)
                    #pragma unroll
                    for (int j = 0; j < 4; j++) {
                        const int row = Q0 + mt * 16 + g + ((j >> 1) << 3);
                        const int col = j0 + nt * 8 + tg * 2 + (j & 1);
                        if (col > row) S[mt][nt][j] = -1e30f;
                    }
        }

        uint32_t pa0[2][4], pa1[2][4];
        #pragma unroll
        for (int mt = 0; mt < 2; mt++) {
            #pragma unroll
            for (int h = 0; h < 2; h++) {
                const int rg = mt * 2 + h;
                float v0 = S[mt][0][h * 2], v1 = S[mt][0][h * 2 + 1];
                float v2 = S[mt][1][h * 2], v3 = S[mt][1][h * 2 + 1];
                float v4 = S[mt][2][h * 2], v5 = S[mt][2][h * 2 + 1];
                float v6 = S[mt][3][h * 2], v7 = S[mt][3][h * 2 + 1];
                float mx = fmaxf(fmaxf(fmaxf(v0, v1), fmaxf(v2, v3)),
                                 fmaxf(fmaxf(v4, v5), fmaxf(v6, v7)));
                mx = fmaxf(mx, __shfl_xor_sync(0xFFFFFFFFu, mx, 1));
                mx = fmaxf(mx, __shfl_xor_sync(0xFFFFFFFFu, mx, 2));
                const float mnew = fmaxf(m[rg], mx);
                const float sc   = ex2(m[rg] - mnew);
                m[rg] = mnew;
                const float p0 = ex2(v0 - mnew), p1 = ex2(v1 - mnew);
                const float p2 = ex2(v2 - mnew), p3 = ex2(v3 - mnew);
                const float p4 = ex2(v4 - mnew), p5 = ex2(v5 - mnew);
                const float p6 = ex2(v6 - mnew), p7 = ex2(v7 - mnew);
                lsum[rg] = lsum[rg] * sc +
                           ((p0 + p1) + (p2 + p3)) + ((p4 + p5) + (p6 + p7));
                #pragma unroll
                for (int n = 0; n < 8; n++) {
                    O[mt][n][h * 2]     *= sc;
                    O[mt][n][h * 2 + 1] *= sc;
                }
                pa0[mt][h]     = pack2h(p0, p1);
                pa0[mt][2 + h] = pack2h(p2, p3);
                pa1[mt][h]     = pack2h(p4, p5);
                pa1[mt][2 + h] = pack2h(p6, p7);
            }
        }

        const uint32_t vb0 = sbVh + (uint32_t)((j0 + vkey) * APAD + voff) * 2;
        const uint32_t vb1 = sbVh + (uint32_t)((j0 + 16 + vkey) * APAD + voff) * 2;
        #pragma unroll
        for (int nc = 0; nc < 4; nc++) {
            uint32_t v0[4], v1[4];
            ldsm_x4t(vb0 + nc * 32, v0);
            ldsm_x4t(vb1 + nc * 32, v1);
            #pragma unroll
            for (int mt = 0; mt < 2; mt++) {
                mma_fp16(O[mt][nc * 2],     pa0[mt], v0[0], v0[1]);
                mma_fp16(O[mt][nc * 2 + 1], pa0[mt], v0[2], v0[3]);
                mma_fp16(O[mt][nc * 2],     pa1[mt], v1[0], v1[1]);
                mma_fp16(O[mt][nc * 2 + 1], pa1[mt], v1[2], v1[3]);
            }
        }
    }

    // ---- epilogue: quad-reduce l, normalize, store ----
    float inv[4];
    #pragma unroll
    for (int rg = 0; rg < 4; rg++) {
        float ls = lsum[rg];
        ls += __shfl_xor_sync(0xFFFFFFFFu, ls, 1);
        ls += __shfl_xor_sync(0xFFFFFFFFu, ls, 2);
        inv[rg] = 1.f / ls;
    }
    float* ob = out + ((size_t)b * TT) * DKV;
    #pragma unroll
    for (int mt = 0; mt < 2; mt++) {
        #pragma unroll
        for (int h = 0; h < 2; h++) {
            const int row = Q0 + mt * 16 + g + h * 8;
            const float iv = inv[mt * 2 + h];
            #pragma unroll
            for (int n = 0; n < 8; n++) {
                *(float2*)(ob + (size_t)row * DKV + n * 8 + tg * 2) =
                    make_float2(O[mt][n][h * 2] * iv, O[mt][n][h * 2 + 1] * iv);
            }
        }
    }
}

// ---------------------------------------------------------------------------
// kernel_launch — graph-capturable, allocation-free
// ---------------------------------------------------------------------------
extern "C" void kernel_launch(void* const* d_in, const int* in_sizes, int n_in,
                              void* d_out, int out_size) {
    const float* x  = (const float*)d_in[0];
    const float* Wq = (const float*)d_in[1];
    const float* Wk = (const float*)d_in[2];
    const float* Wv = (const float*)d_in[3];
    float* out = (float*)d_out;
    (void)in_sizes; (void)n_in; (void)out_size;

    wconv_kernel<<<36, 256>>>(Wq, Wk, Wv);

    const int proj_smem = SM_ELEMS * (int)sizeof(__half);        // 76.8 KB
    cudaFuncSetAttribute(proj_mma_kernel,
                         cudaFuncAttributeMaxDynamicSharedMemorySize, proj_smem);
    proj_mma_kernel<<<BT / BM, 512, proj_smem>>>(x);

    const int attn_smem = 2 * KV_SZ * (int)sizeof(__half);       // 72 KB
    cudaFuncSetAttribute(attn_mma_kernel,
                         cudaFuncAttributeMaxDynamicSharedMemorySize, attn_smem);
    attn_mma_kernel<<<BATCH, 256, attn_smem>>>(out);
}

// round 13
// speedup vs baseline: 1.2759x; 1.2468x over previous
#include <cuda_runtime.h>
#include <cuda_fp16.h>
#include <cstdint>

// Problem constants
#define BATCH 256
#define TT    256
#define DM    384
#define DKV   64
#define BT    (BATCH*TT)

// ---------------------------------------------------------------------------
// Scratch: only W^T fp16 remains in gmem. q/k/v never leave shared memory.
// ---------------------------------------------------------------------------
__device__ __align__(16) __half g_wh[192 * DM];

// ---------------------------------------------------------------------------
// PTX helpers (sm_80-era: mma.sync + ldmatrix + cp.async, valid at compute_103)
// ---------------------------------------------------------------------------
__device__ __forceinline__ uint32_t smem_u32(const void* p) {
    uint32_t a;
    asm("{ .reg .u64 t; cvta.to.shared.u64 t, %1; cvt.u32.u64 %0, t; }"
        : "=r"(a) : "l"(p));
    return a;
}
__device__ __forceinline__ void ldsm_x4(uint32_t addr, uint32_t* r) {
    asm volatile("ldmatrix.sync.aligned.m8n8.x4.shared.b16 {%0,%1,%2,%3}, [%4];"
                 : "=r"(r[0]), "=r"(r[1]), "=r"(r[2]), "=r"(r[3]) : "r"(addr));
}
__device__ __forceinline__ void ldsm_x4t(uint32_t addr, uint32_t* r) {
    asm volatile("ldmatrix.sync.aligned.m8n8.x4.trans.shared.b16 {%0,%1,%2,%3}, [%4];"
                 : "=r"(r[0]), "=r"(r[1]), "=r"(r[2]), "=r"(r[3]) : "r"(addr));
}
__device__ __forceinline__ void mma_fp16(float* c, const uint32_t* a,
                                         uint32_t b0, uint32_t b1) {
    asm volatile(
        "mma.sync.aligned.m16n8k16.row.col.f32.f16.f16.f32 "
        "{%0,%1,%2,%3}, {%4,%5,%6,%7}, {%8,%9}, {%0,%1,%2,%3};"
        : "+f"(c[0]), "+f"(c[1]), "+f"(c[2]), "+f"(c[3])
        : "r"(a[0]), "r"(a[1]), "r"(a[2]), "r"(a[3]), "r"(b0), "r"(b1));
}
__device__ __forceinline__ float ex2(float x) {
    float y;
    asm("ex2.approx.ftz.f32 %0, %1;" : "=f"(y) : "f"(x));
    return y;
}
__device__ __forceinline__ void split2h(float x, float y, uint32_t& h, uint32_t& l) {
    __half h0 = __float2half_rn(x), h1 = __float2half_rn(y);
    __half l0 = __float2half_rn(x - __half2float(h0));
    __half l1 = __float2half_rn(y - __half2float(h1));
    __half2 hp = __halves2half2(h0, h1);
    __half2 lp = __halves2half2(l0, l1);
    h = *(uint32_t*)&hp; l = *(uint32_t*)&lp;
}
__device__ __forceinline__ uint32_t pack2h(float x, float y) {
    __half2 hp = __halves2half2(__float2half_rn(x), __float2half_rn(y));
    return *(uint32_t*)&hp;
}
#define CP_ASYNC16(dst, src) \
    asm volatile("cp.async.cg.shared.global [%0], [%1], 16;" \
                 :: "r"(dst), "l"(src) : "memory")
#define CP_COMMIT() asm volatile("cp.async.commit_group;" ::: "memory")
#define CP_WAIT(n)  asm volatile("cp.async.wait_group %0;" :: "n"(n) : "memory")

// ---------------------------------------------------------------------------
// Kernel 0: W^T fp16 conversion, coalesced reads via smem transpose.
// ---------------------------------------------------------------------------
__global__ void wconv_kernel(const float* __restrict__ Wq,
                             const float* __restrict__ Wk,
                             const float* __restrict__ Wv) {
    __shared__ float t[32][65];
    const int mat = blockIdx.x / 12;          // 0..2
    const int k0  = (blockIdx.x % 12) * 32;
    const float* W = (mat == 0) ? Wq : (mat == 1) ? Wk : Wv;
    const int tid = threadIdx.x;

    {
        const int n  = tid & 63;
        const int kl = tid >> 6;
        #pragma unroll
        for (int i = 0; i < 8; i++) {
            const int k = kl + i * 4;
            t[k][n] = W[(size_t)(k0 + k) * DKV + n];
        }
    }
    __syncthreads();
    {
        const int kl = tid & 31;
        const int nl = tid >> 5;
        #pragma unroll
        for (int i = 0; i < 8; i++) {
            const int n = nl + i * 8;
            g_wh[(size_t)(mat * 64 + n) * DM + k0 + kl] = __float2half_rn(t[kl][n]);
        }
    }
}

// ---------------------------------------------------------------------------
// FUSED kernel: per-batch QKV projection (2 x R10 proj pipeline, epilogue to
// smem) followed directly by causal attention on the smem tiles.
//   Grid 256 (1 CTA per batch), 256 threads, no q/k/v gmem round trip.
// ---------------------------------------------------------------------------
#define BM   128
#define BKS  32
#define NKS  (DM / BKS)
#define PAD  40
#define APAD 72

#define A_SZ (BM * PAD)          // 5120
#define B_SZ (192 * PAD)         // 7680
#define OFF_A(buf)  ((buf) * A_SZ)
#define OFF_B(buf)  (3 * A_SZ + (buf) * B_SZ)
#define OFF_QH      (3 * A_SZ + 3 * B_SZ)          // 38400
#define OFF_QL      (OFF_QH + TT * APAD)           // +18432
#define OFF_KH      (OFF_QL + TT * APAD)
#define OFF_VH      (OFF_KH + TT * APAD)
#define SM_TOT      (OFF_VH + TT * APAD)           // 112128 fp16 = 224256 B

__global__ void __launch_bounds__(256, 1) fused_kernel(const float* __restrict__ X,
                                                       float* __restrict__ out) {
    extern __shared__ __half sm[];
    const uint32_t sb = smem_u32(sm);

    const int b    = blockIdx.x;
    const int tid  = threadIdx.x;
    const int lane = tid & 31;
    const int wid  = tid >> 5;
    const int warp_m = wid & 3;          // 4 warps along M: 32 rows each
    const int warp_n = wid >> 2;         // 2 warps along N: 96 cols each

    // =====================  PHASE 1: projection (2 halves)  =================
    for (int hf = 0; hf < 2; hf++) {
        const int row0 = b * TT + hf * BM;      // global X row base

        float acc[2][12][4];
        #pragma unroll
        for (int m = 0; m < 2; m++)
            #pragma unroll
            for (int n = 0; n < 12; n++)
                #pragma unroll
                for (int j = 0; j < 4; j++) acc[m][n][j] = 0.f;

        float4 xa[4];
        const int br  = tid >> 2;
        const int bc8 = tid & 3;

        auto cp_b = [&](int ks, int buf) {
            const int k0 = ks * BKS;
            #pragma unroll
            for (int i = 0; i < 3; i++) {
                int r = br + i * 64;
                uint32_t dst = sb + (uint32_t)(OFF_B(buf) + r * PAD + bc8 * 8) * 2;
                CP_ASYNC16(dst, g_wh + r * DM + k0 + bc8 * 8);
            }
        };
        auto load_x = [&](int ks) {
            const int k0 = ks * BKS;
            #pragma unroll
            for (int i = 0; i < 4; i++) {
                int f  = tid + i * 256;
                int r  = f >> 3;
                int c4 = f & 7;
                xa[i] = *(const float4*)(X + (size_t)(row0 + r) * DM + k0 + c4 * 4);
            }
        };
        auto store_x = [&](int buf) {
            #pragma unroll
            for (int i = 0; i < 4; i++) {
                int f  = tid + i * 256;
                int r  = f >> 3;
                int c4 = f & 7;
                float4 v = xa[i];
                *(uint2*)(sm + OFF_A(buf) + r * PAD + c4 * 4) =
                    make_uint2(pack2h(v.x, v.y), pack2h(v.z, v.w));
            }
        };

        cp_b(0, 0); CP_COMMIT();
        cp_b(1, 1); CP_COMMIT();
        load_x(0);
        store_x(0);
        CP_WAIT(1);
        __syncthreads();

        for (int ks = 0; ks < NKS; ks++) {
            if (ks + 2 < NKS) { cp_b(ks + 2, (ks + 2) % 3); CP_COMMIT(); }
            if (ks + 1 < NKS) load_x(ks + 1);

            const uint32_t a_base = sb + OFF_A(ks % 3) * 2;
            const uint32_t b_base = sb + OFF_B(ks % 3) * 2;

            #pragma unroll
            for (int kk = 0; kk < 2; kk++) {
                uint32_t ah[2][4];
                const int arow_l = (lane & 15);
                const int acol   = kk * 16 + ((lane >> 4) << 3);
                #pragma unroll
                for (int mt = 0; mt < 2; mt++) {
                    const int arow = warp_m * 32 + mt * 16 + arow_l;
                    ldsm_x4(a_base + (uint32_t)(arow * PAD + acol) * 2, ah[mt]);
                }
                const int brow_l = (lane & 7) + ((lane & 16) >> 1);
                const int bcol   = kk * 16 + (lane & 8);
                #pragma unroll
                for (int g = 0; g < 6; g++) {
                    uint32_t bh[4];
                    const int brow = warp_n * 96 + g * 16 + brow_l;
                    ldsm_x4(b_base + (uint32_t)(brow * PAD + bcol) * 2, bh);
                    #pragma unroll
                    for (int mt = 0; mt < 2; mt++) {
                        #pragma unroll
                        for (int h = 0; h < 2; h++) {
                            mma_fp16(acc[mt][g * 2 + h], ah[mt],
                                     bh[h * 2], bh[h * 2 + 1]);
                        }
                    }
                }
            }

            if (ks + 1 < NKS) {
                store_x((ks + 1) % 3);
                if (ks + 2 < NKS) { CP_WAIT(1); }
                else              { CP_WAIT(0); }
                __syncthreads();
            }
        }

        // ---- epilogue: q -> smem hi/lo fp16, k/v -> smem fp16 ----
        const int gi = lane >> 2;
        const int ti = lane & 3;
        #pragma unroll
        for (int mt = 0; mt < 2; mt++) {
            const int lrow = hf * BM + warp_m * 32 + mt * 16 + gi;  // 0..255
            #pragma unroll
            for (int nt = 0; nt < 12; nt++) {
                const int col = warp_n * 96 + nt * 8 + ti * 2;
                if (col < 64) {
                    uint32_t h0, l0, h1, l1;
                    split2h(acc[mt][nt][0], acc[mt][nt][1], h0, l0);
                    split2h(acc[mt][nt][2], acc[mt][nt][3], h1, l1);
                    *(uint32_t*)(sm + OFF_QH + lrow * APAD + col) = h0;
                    *(uint32_t*)(sm + OFF_QL + lrow * APAD + col) = l0;
                    *(uint32_t*)(sm + OFF_QH + (lrow + 8) * APAD + col) = h1;
                    *(uint32_t*)(sm + OFF_QL + (lrow + 8) * APAD + col) = l1;
                } else {
                    const int o = (col < 128) ? OFF_KH : OFF_VH;
                    const int c = col & 63;
                    *(uint32_t*)(sm + o + lrow * APAD + c) =
                        pack2h(acc[mt][nt][0], acc[mt][nt][1]);
                    *(uint32_t*)(sm + o + (lrow + 8) * APAD + c) =
                        pack2h(acc[mt][nt][2], acc[mt][nt][3]);
                }
            }
        }
        __syncthreads();
    }

    // =====================  PHASE 2: causal attention  ======================
    const int qb = (wid < 4) ? wid : (11 - wid);   // SMSP balance
    const int Q0 = qb * 32;
    const int g  = lane >> 2;
    const int tg = lane & 3;
    const float SC = 0.125f * 1.44269504f;         // applied to scores

    // Q fragments from smem (hi/lo)
    uint32_t qh[2][4][4], ql[2][4][4];
    #pragma unroll
    for (int mt = 0; mt < 2; mt++) {
        #pragma unroll
        for (int kk = 0; kk < 4; kk++) {
            const int arow = Q0 + mt * 16 + (lane & 15);
            const int acol = kk * 16 + ((lane >> 4) << 3);
            ldsm_x4(sb + (uint32_t)(OFF_QH + arow * APAD + acol) * 2, qh[mt][kk]);
            ldsm_x4(sb + (uint32_t)(OFF_QL + arow * APAD + acol) * 2, ql[mt][kk]);
        }
    }

    float m[4] = {-1e30f, -1e30f, -1e30f, -1e30f};
    float lsum[4] = {0.f, 0.f, 0.f, 0.f};
    float O[2][8][4];
    #pragma unroll
    for (int mt = 0; mt < 2; mt++)
        #pragma unroll
        for (int n = 0; n < 8; n++)
            #pragma unroll
            for (int j = 0; j < 4; j++) O[mt][n][j] = 0.f;

    const int krow = (lane & 7) + ((lane & 16) >> 1);
    const int koff = (lane & 8);
    const int vkey = lane & 15;
    const int voff = (lane >> 4) << 3;

    const int nrounds = qb + 1;
    for (int kr = 0; kr < nrounds; kr++) {
        const int j0 = kr * 32;
        const bool msk = (kr == qb);

        float S[2][4][4];
        #pragma unroll
        for (int mt = 0; mt < 2; mt++)
            #pragma unroll
            for (int nt = 0; nt < 4; nt++)
                #pragma unroll
                for (int j = 0; j < 4; j++) S[mt][nt][j] = 0.f;

        const uint32_t kb0 = sb + (uint32_t)(OFF_KH + (j0 + krow) * APAD + koff) * 2;
        const uint32_t kb1 = sb + (uint32_t)(OFF_KH + (j0 + 16 + krow) * APAD + koff) * 2;
        #pragma unroll
        for (int kk = 0; kk < 4; kk++) {
            uint32_t b0[4], b1[4];
            ldsm_x4(kb0 + kk * 32, b0);
            ldsm_x4(kb1 + kk * 32, b1);
            #pragma unroll
            for (int mt = 0; mt < 2; mt++) {
                mma_fp16(S[mt][0], qh[mt][kk], b0[0], b0[1]);
                mma_fp16(S[mt][1], qh[mt][kk], b0[2], b0[3]);
                mma_fp16(S[mt][2], qh[mt][kk], b1[0], b1[1]);
                mma_fp16(S[mt][3], qh[mt][kk], b1[2], b1[3]);
                mma_fp16(S[mt][0], ql[mt][kk], b0[0], b0[1]);
                mma_fp16(S[mt][1], ql[mt][kk], b0[2], b0[3]);
                mma_fp16(S[mt][2], ql[mt][kk], b1[0], b1[1]);
                mma_fp16(S[mt][3], ql[mt][kk], b1[2], b1[3]);
            }
        }

        if (msk) {
            #pragma unroll
            for (int mt = 0; mt < 2; mt++)
                #pragma unroll
                for (int nt = 0; nt < 4; nt++)
                    #pragma unroll
                    for (int j = 0; j < 4; j++) {
                        const int row = Q0 + mt * 16 + g + ((j >> 1) << 3);
                        const int col = j0 + nt * 8 + tg * 2 + (j & 1);
                        if (col > row) S[mt][nt][j] = -3e38f;
                    }
        }

        uint32_t pa0[2][4], pa1[2][4];
        #pragma unroll
        for (int mt = 0; mt < 2; mt++) {
            #pragma unroll
            for (int h = 0; h < 2; h++) {
                const int rg = mt * 2 + h;
                float v0 = S[mt][0][h * 2] * SC, v1 = S[mt][0][h * 2 + 1] * SC;
                float v2 = S[mt][1][h * 2] * SC, v3 = S[mt][1][h * 2 + 1] * SC;
                float v4 = S[mt][2][h * 2] * SC, v5 = S[mt][2][h * 2 + 1] * SC;
                float v6 = S[mt][3][h * 2] * SC, v7 = S[mt][3][h * 2 + 1] * SC;
                float mx = fmaxf(fmaxf(fmaxf(v0, v1), fmaxf(v2, v3)),
                                 fmaxf(fmaxf(v4, v5), fmaxf(v6, v7)));
                mx = fmaxf(mx, __shfl_xor_sync(0xFFFFFFFFu, mx, 1));
                mx = fmaxf(mx, __shfl_xor_sync(0xFFFFFFFFu, mx, 2));
                const float mnew = fmaxf(m[rg], mx);
                const float sc   = ex2(m[rg] - mnew);
                m[rg] = mnew;
                const float p0 = ex2(v0 - mnew), p1 = ex2(v1 - mnew);
                const float p2 = ex2(v2 - mnew), p3 = ex2(v3 - mnew);
                const float p4 = ex2(v4 - mnew), p5 = ex2(v5 - mnew);
                const float p6 = ex2(v6 - mnew), p7 = ex2(v7 - mnew);
                lsum[rg] = lsum[rg] * sc +
                           ((p0 + p1) + (p2 + p3)) + ((p4 + p5) + (p6 + p7));
                #pragma unroll
                for (int n = 0; n < 8; n++) {
                    O[mt][n][h * 2]     *= sc;
                    O[mt][n][h * 2 + 1] *= sc;
                }
                pa0[mt][h]     = pack2h(p0, p1);
                pa0[mt][2 + h] = pack2h(p2, p3);
                pa1[mt][h]     = pack2h(p4, p5);
                pa1[mt][2 + h] = pack2h(p6, p7);
            }
        }

        const uint32_t vb0 = sb + (uint32_t)(OFF_VH + (j0 + vkey) * APAD + voff) * 2;
        const uint32_t vb1 = sb + (uint32_t)(OFF_VH + (j0 + 16 + vkey) * APAD + voff) * 2;
        #pragma unroll
        for (int nc = 0; nc < 4; nc++) {
            uint32_t v0[4], v1[4];
            ldsm_x4t(vb0 + nc * 32, v0);
            ldsm_x4t(vb1 + nc * 32, v1);
            #pragma unroll
            for (int mt = 0; mt < 2; mt++) {
                mma_fp16(O[mt][nc * 2],     pa0[mt], v0[0], v0[1]);
                mma_fp16(O[mt][nc * 2 + 1], pa0[mt], v0[2], v0[3]);
                mma_fp16(O[mt][nc * 2],     pa1[mt], v1[0], v1[1]);
                mma_fp16(O[mt][nc * 2 + 1], pa1[mt], v1[2], v1[3]);
            }
        }
    }

    // ---- epilogue: quad-reduce l, normalize, store ----
    float inv[4];
    #pragma unroll
    for (int rg = 0; rg < 4; rg++) {
        float ls = lsum[rg];
        ls += __shfl_xor_sync(0xFFFFFFFFu, ls, 1);
        ls += __shfl_xor_sync(0xFFFFFFFFu, ls, 2);
        inv[rg] = 1.f / ls;
    }
    float* ob = out + ((size_t)b * TT) * DKV;
    #pragma unroll
    for (int mt = 0; mt < 2; mt++) {
        #pragma unroll
        for (int h = 0; h < 2; h++) {
            const int row = Q0 + mt * 16 + g + h * 8;
            const float iv = inv[mt * 2 + h];
            #pragma unroll
            for (int n = 0; n < 8; n++) {
                *(float2*)(ob + (size_t)row * DKV + n * 8 + tg * 2) =
                    make_float2(O[mt][n][h * 2] * iv, O[mt][n][h * 2 + 1] * iv);
            }
        }
    }
}

// ---------------------------------------------------------------------------
// kernel_launch — graph-capturable, allocation-free
// ---------------------------------------------------------------------------
extern "C" void kernel_launch(void* const* d_in, const int* in_sizes, int n_in,
                              void* d_out, int out_size) {
    const float* x  = (const float*)d_in[0];
    const float* Wq = (const float*)d_in[1];
    const float* Wk = (const float*)d_in[2];
    const float* Wv = (const float*)d_in[3];
    float* out = (float*)d_out;
    (void)in_sizes; (void)n_in; (void)out_size;

    wconv_kernel<<<36, 256>>>(Wq, Wk, Wv);

    const int fused_smem = SM_TOT * (int)sizeof(__half);   // 224256 B
    cudaFuncSetAttribute(fused_kernel,
                         cudaFuncAttributeMaxDynamicSharedMemorySize, fused_smem);
    fused_kernel<<<BATCH, 256, fused_smem>>>(x, out);
}